// round 9
// baseline (speedup 1.0000x reference)
#include <cuda_runtime.h>
#include <cuda_fp16.h>

#define DD 48
#define HH 256
#define WW 256
#define HM 128
#define WM 128
#define PHN 4

// fp16-packed image: one half2 (ch0, ch1) per pixel. 48*256*256*4B = 12.6 MB.
__device__ __half2 g_img_h2[DD * HH * WW];

// ---------------------------------------------------------------------------
// Pre-pass: channel-0 copy + fp16 pack, one image read.
// Each thread handles 2 pixels (one float4).
// ---------------------------------------------------------------------------
__global__ __launch_bounds__(256) void convert_kernel(
    const float4* __restrict__ img, float4* __restrict__ out, int n4)
{
    int i = blockIdx.x * blockDim.x + threadIdx.x;
    if (i >= n4) return;
    float4 v = __ldg(img + i);          // pixels 2i, 2i+1
    out[i] = v;                         // channel-0 passthrough
    __half2 a = __floats2half2_rn(v.x, v.y);
    __half2 b = __floats2half2_rn(v.z, v.w);
    g_img_h2[2 * i]     = a;
    g_img_h2[2 * i + 1] = b;
}

__device__ __forceinline__ float2 h2_as_f2(unsigned int u)
{
    __half2 h = *reinterpret_cast<__half2*>(&u);
    return __half22float2(h);
}

// ---------------------------------------------------------------------------
// Fused mvf-upsample + warp. One thread per output voxel (p,z,y,x);
// block = full W row (256 threads) -> warp spans 32 consecutive x.
// Image gather: per (dz,dy) row one aligned 8B pair load + predicated second
// when the x-corner pair straddles a chunk boundary (~50%).
// ---------------------------------------------------------------------------
__global__ __launch_bounds__(256) void mvf_warp_kernel(
    const float* __restrict__ mvf,     // [PHN][3][DD][HM][WM]
    float* __restrict__ out)           // [5][DD][HH][WW][2]
{
    const int x = threadIdx.x;      // 0..255
    const int y = blockIdx.x;       // 0..255
    const int z = blockIdx.y;       // 0..47
    const int p = blockIdx.z;       // 0..3

    // ---- MVF upsample source coords (linear 128->256, clamp) ----
    float fy = fminf(fmaxf(y * 0.5f - 0.25f, 0.0f), (float)(HM - 1));
    float fx = fminf(fmaxf(x * 0.5f - 0.25f, 0.0f), (float)(WM - 1));
    int   y0 = (int)fy;
    int   x0 = (int)fx;
    float wy = fy - (float)y0;
    float wx = fx - (float)x0;
    int   y1 = min(y0 + 1, HM - 1);
    int   x1 = min(x0 + 1, WM - 1);

    const int mbase = ((p * 3) * DD + z) * (HM * WM);
    const int cstr  = DD * HM * WM;

    float m[3];
    #pragma unroll
    for (int c = 0; c < 3; ++c) {
        const float* mp = mvf + mbase + c * cstr;
        float v00 = __ldg(mp + y0 * WM + x0);
        float v01 = __ldg(mp + y0 * WM + x1);
        float v10 = __ldg(mp + y1 * WM + x0);
        float v11 = __ldg(mp + y1 * WM + x1);
        float r0 = v00 + wx * (v01 - v00);
        float r1 = v10 + wx * (v11 - v10);
        m[c] = r0 + wy * (r1 - r0);
    }

    // ---- absolute sample coordinates, flow scaled by (1,2,2) ----
    float cz = (float)z + m[0];
    float cy = (float)y + 2.0f * m[1];
    float cx = (float)x + 2.0f * m[2];

    float zf = floorf(cz), yf = floorf(cy), xf = floorf(cx);
    int   zi = (int)zf,    yi = (int)yf,    xi = (int)xf;
    float wz  = cz - zf;
    float wyy = cy - yf;
    float wxx = cx - xf;

    // ---- x-corner handling (shared across the 4 gather rows) ----
    int  c0 = min(max(xi,     0), WW - 1);
    int  c1 = min(max(xi + 1, 0), WW - 1);
    int  b0 = c0 >> 1;                      // 8B chunk index within a row
    int  b1 = c1 >> 1;
    bool hi0   = (c0 & 1);
    bool hi1   = (c1 & 1);
    bool need2 = (b1 != b0);
    float wx0 = ((unsigned)xi       < (unsigned)WW) ? (1.0f - wxx) : 0.0f;
    float wx1 = ((unsigned)(xi + 1) < (unsigned)WW) ? wxx          : 0.0f;

    const uint2* img_pair = (const uint2*)g_img_h2;   // pair i = pixels {2i,2i+1}

    float acc0 = 0.0f, acc1 = 0.0f;
    #pragma unroll
    for (int dz = 0; dz < 2; ++dz) {
        int zz = zi + dz;
        float wzv = dz ? wz : (1.0f - wz);
        int  zc = min(max(zz, 0), DD - 1);
        bool zok = ((unsigned)zz < (unsigned)DD);
        #pragma unroll
        for (int dy = 0; dy < 2; ++dy) {
            int yy = yi + dy;
            float wyv = dy ? wyy : (1.0f - wyy);
            int  yc = min(max(yy, 0), HH - 1);
            bool yok = ((unsigned)yy < (unsigned)HH);
            float wb = (zok && yok) ? (wzv * wyv) : 0.0f;

            int rowp = ((zc * HH + yc) * WW) >> 1;    // pair index of row start
            uint2 qa = __ldg(img_pair + rowp + b0);
            uint2 qb = qa;
            if (need2) qb = __ldg(img_pair + rowp + b1);

            float2 p0 = h2_as_f2(hi0 ? qa.y : qa.x);
            float2 p1 = h2_as_f2(hi1 ? qb.y : qb.x);

            float w0 = wb * wx0;
            float w1 = wb * wx1;
            acc0 = fmaf(w0, p0.x, fmaf(w1, p1.x, acc0));
            acc1 = fmaf(w0, p0.y, fmaf(w1, p1.y, acc1));
        }
    }

    float2* o = (float2*)out + (((1 + p) * DD + z) * HH + y) * WW + x;
    *o = make_float2(acc0, acc1);
}

extern "C" void kernel_launch(void* const* d_in, const int* in_sizes, int n_in,
                              void* d_out, int out_size)
{
    const float* image = (const float*)d_in[0];   // 6291456 floats
    const float* mvf   = (const float*)d_in[1];   // 9437184 floats
    float* out = (float*)d_out;                   // 31457280 floats

    // pre-pass: channel-0 copy + fp16 pack
    const int n4 = (DD * HH * WW * 2) / 4;        // 1572864 float4 (2 px each)
    convert_kernel<<<(n4 + 255) / 256, 256>>>((const float4*)image, (float4*)out, n4);

    // channels 1..4: fused upsample + warp
    dim3 grid(HH, DD, PHN);
    mvf_warp_kernel<<<grid, 256>>>(mvf, out);
}

// round 10
// speedup vs baseline: 1.0055x; 1.0055x over previous
#include <cuda_runtime.h>
#include <cuda_fp16.h>

#define DD 48
#define HH 256
#define WW 256
#define HM 128
#define WM 128
#define PHN 4

// fp16-packed image: one half2 (ch0, ch1) per pixel. 48*256*256*4B = 12.6 MB.
__device__ __half2 g_img_h2[DD * HH * WW];

// ---------------------------------------------------------------------------
// Pre-pass: channel-0 copy + fp16 pack. 4 pixels (2 float4) per thread.
// ---------------------------------------------------------------------------
__global__ __launch_bounds__(256) void convert_kernel(
    const float4* __restrict__ img, float4* __restrict__ out, int ng)
{
    int i = blockIdx.x * blockDim.x + threadIdx.x;
    if (i >= ng) return;
    float4 v0 = __ldg(img + 2 * i);
    float4 v1 = __ldg(img + 2 * i + 1);
    out[2 * i]     = v0;
    out[2 * i + 1] = v1;
    __half2 a = __floats2half2_rn(v0.x, v0.y);
    __half2 b = __floats2half2_rn(v0.z, v0.w);
    __half2 c = __floats2half2_rn(v1.x, v1.y);
    __half2 d = __floats2half2_rn(v1.z, v1.w);
    uint4 pk;
    pk.x = *(unsigned int*)&a;
    pk.y = *(unsigned int*)&b;
    pk.z = *(unsigned int*)&c;
    pk.w = *(unsigned int*)&d;
    ((uint4*)g_img_h2)[i] = pk;
}

__device__ __forceinline__ float2 h2_as_f2(unsigned int u)
{
    __half2 h = *reinterpret_cast<__half2*>(&u);
    return __half22float2(h);
}

// Branchless predicated second-chunk load: qb = need2 ? *(addr+8) : qa
__device__ __forceinline__ void pred_load2(unsigned int& bx, unsigned int& by,
                                           unsigned int ax, unsigned int ay,
                                           int need2, const void* addr)
{
    asm("{\n\t"
        ".reg .pred p;\n\t"
        "setp.ne.s32 p, %4, 0;\n\t"
        "mov.u32 %0, %2;\n\t"
        "mov.u32 %1, %3;\n\t"
        "@p ld.global.nc.v2.u32 {%0, %1}, [%5+8];\n\t"
        "}"
        : "=r"(bx), "=r"(by)
        : "r"(ax), "r"(ay), "r"(need2), "l"(addr));
}

// ---------------------------------------------------------------------------
// Fused mvf-upsample + warp. One thread per output voxel (p,z,y,x);
// block = full W row (256 threads) -> warp spans 32 consecutive x.
// Gather: per (dz,dy) row one aligned 8B pair load + branchless predicated
// second chunk on straddle. Incremental row addressing (2 byte deltas).
// ---------------------------------------------------------------------------
__global__ __launch_bounds__(256) void mvf_warp_kernel(
    const float* __restrict__ mvf,     // [PHN][3][DD][HM][WM]
    float* __restrict__ out)           // [5][DD][HH][WW][2]
{
    const int x = threadIdx.x;      // 0..255
    const int y = blockIdx.x;       // 0..255
    const int z = blockIdx.y;       // 0..47
    const int p = blockIdx.z;       // 0..3

    // ---- MVF upsample source coords (linear 128->256, clamp) ----
    float fy = fminf(fmaxf(y * 0.5f - 0.25f, 0.0f), (float)(HM - 1));
    float fx = fminf(fmaxf(x * 0.5f - 0.25f, 0.0f), (float)(WM - 1));
    int   y0 = (int)fy;
    int   x0 = (int)fx;
    float wy = fy - (float)y0;
    float wx = fx - (float)x0;
    int   y1 = min(y0 + 1, HM - 1);
    int   x1 = min(x0 + 1, WM - 1);

    const int mbase = ((p * 3) * DD + z) * (HM * WM);
    const int cstr  = DD * HM * WM;

    float m[3];
    #pragma unroll
    for (int c = 0; c < 3; ++c) {
        const float* mp = mvf + mbase + c * cstr;
        float v00 = __ldg(mp + y0 * WM + x0);
        float v01 = __ldg(mp + y0 * WM + x1);
        float v10 = __ldg(mp + y1 * WM + x0);
        float v11 = __ldg(mp + y1 * WM + x1);
        float r0 = v00 + wx * (v01 - v00);
        float r1 = v10 + wx * (v11 - v10);
        m[c] = r0 + wy * (r1 - r0);
    }

    // ---- absolute sample coordinates, flow scaled by (1,2,2) ----
    float cz = (float)z + m[0];
    float cy = (float)y + 2.0f * m[1];
    float cx = (float)x + 2.0f * m[2];

    float zf = floorf(cz), yf = floorf(cy), xf = floorf(cx);
    int   zi = (int)zf,    yi = (int)yf,    xi = (int)xf;
    float wz  = cz - zf;
    float wyy = cy - yf;
    float wxx = cx - xf;

    // ---- x-corner prep (shared across the 4 gather rows) ----
    int  c0 = min(max(xi,     0), WW - 1);
    int  c1 = min(max(xi + 1, 0), WW - 1);
    int  b0 = c0 >> 1;
    int  need2 = (c1 >> 1) - b0;            // 0 or 1
    bool hi0 = (c0 & 1);
    bool hi1 = (c1 & 1);
    float wx0 = ((unsigned)xi       < (unsigned)WW) ? (1.0f - wxx) : 0.0f;
    float wx1 = ((unsigned)(xi + 1) < (unsigned)WW) ? wxx          : 0.0f;

    // ---- z/y rows: base address + two byte deltas ----
    int  zc0 = min(max(zi,     0), DD - 1);
    int  zc1 = min(max(zi + 1, 0), DD - 1);
    int  yc0 = min(max(yi,     0), HH - 1);
    int  yc1 = min(max(yi + 1, 0), HH - 1);
    bool zok0 = ((unsigned)zi       < (unsigned)DD);
    bool zok1 = ((unsigned)(zi + 1) < (unsigned)DD);
    bool yok0 = ((unsigned)yi       < (unsigned)HH);
    bool yok1 = ((unsigned)(yi + 1) < (unsigned)HH);

    float wz0 = 1.0f - wz, wy0 = 1.0f - wyy;
    float wr00 = (zok0 && yok0) ? (wz0 * wy0) : 0.0f;
    float wr01 = (zok0 && yok1) ? (wz0 * wyy) : 0.0f;
    float wr10 = (zok1 && yok0) ? (wz  * wy0) : 0.0f;
    float wr11 = (zok1 && yok1) ? (wz  * wyy) : 0.0f;

    // byte offsets: row (zc,yc) starts at (zc*HH+yc)*WW*4 bytes; chunk b0 at +b0*8
    const char* base = (const char*)g_img_h2;
    const char* a00 = base + (((long)(zc0 * HH + yc0)) << 10) + ((long)b0 << 3);
    long dyo = (long)(yc1 - yc0) << 10;
    long dzo = (long)(zc1 - zc0) * ((long)HH << 10);
    const char* a01 = a00 + dyo;
    const char* a10 = a00 + dzo;
    const char* a11 = a01 + dzo;

    float acc0 = 0.0f, acc1 = 0.0f;
    const char* addrs[4] = {a00, a01, a10, a11};
    float wrs[4] = {wr00, wr01, wr10, wr11};

    #pragma unroll
    for (int r = 0; r < 4; ++r) {
        uint2 qa = __ldg((const uint2*)addrs[r]);
        unsigned int qbx, qby;
        pred_load2(qbx, qby, qa.x, qa.y, need2, addrs[r]);

        float2 p0 = h2_as_f2(hi0 ? qa.y : qa.x);
        float2 p1 = h2_as_f2(hi1 ? qby  : qbx);

        float w0 = wrs[r] * wx0;
        float w1 = wrs[r] * wx1;
        acc0 = fmaf(w0, p0.x, fmaf(w1, p1.x, acc0));
        acc1 = fmaf(w0, p0.y, fmaf(w1, p1.y, acc1));
    }

    float2* o = (float2*)out + (((1 + p) * DD + z) * HH + y) * WW + x;
    *o = make_float2(acc0, acc1);
}

extern "C" void kernel_launch(void* const* d_in, const int* in_sizes, int n_in,
                              void* d_out, int out_size)
{
    const float* image = (const float*)d_in[0];   // 6291456 floats
    const float* mvf   = (const float*)d_in[1];   // 9437184 floats
    float* out = (float*)d_out;                   // 31457280 floats

    // pre-pass: channel-0 copy + fp16 pack (4 px per thread)
    const int ng = (DD * HH * WW) / 4;            // 786432 groups of 4 px
    convert_kernel<<<(ng + 255) / 256, 256>>>((const float4*)image, (float4*)out, ng);

    // channels 1..4: fused upsample + warp
    dim3 grid(HH, DD, PHN);
    mvf_warp_kernel<<<grid, 256>>>(mvf, out);
}

// round 11
// speedup vs baseline: 1.1650x; 1.1586x over previous
#include <cuda_runtime.h>
#include <cuda_fp16.h>

#define DD 48
#define HH 256
#define WW 256
#define HM 128
#define WM 128
#define PHN 4

// fp16-packed image: one half2 (ch0, ch1) per pixel. 48*256*256*4B = 12.6 MB.
__device__ __half2 g_img_h2[DD * HH * WW];

// ---------------------------------------------------------------------------
// Pre-pass: channel-0 copy + fp16 pack. 4 pixels (2 float4) per thread.
// ---------------------------------------------------------------------------
__global__ __launch_bounds__(256) void convert_kernel(
    const float4* __restrict__ img, float4* __restrict__ out, int ng)
{
    int i = blockIdx.x * blockDim.x + threadIdx.x;
    if (i >= ng) return;
    float4 v0 = __ldg(img + 2 * i);
    float4 v1 = __ldg(img + 2 * i + 1);
    out[2 * i]     = v0;
    out[2 * i + 1] = v1;
    __half2 a = __floats2half2_rn(v0.x, v0.y);
    __half2 b = __floats2half2_rn(v0.z, v0.w);
    __half2 c = __floats2half2_rn(v1.x, v1.y);
    __half2 d = __floats2half2_rn(v1.z, v1.w);
    uint4 pk;
    pk.x = *(unsigned int*)&a;
    pk.y = *(unsigned int*)&b;
    pk.z = *(unsigned int*)&c;
    pk.w = *(unsigned int*)&d;
    ((uint4*)g_img_h2)[i] = pk;
}

__device__ __forceinline__ float2 h2_as_f2(unsigned int u)
{
    __half2 h = *reinterpret_cast<__half2*>(&u);
    return __half22float2(h);
}

// ---------------------------------------------------------------------------
// Fused mvf-upsample + warp. One thread per output voxel (p,z,y,x);
// block = full W row (256 threads) -> warp spans 32 consecutive x.
// 8x LDG.32 image gather, all addressed as one base + {0,dyo,dzo} + (+4 imm).
// 12 mvf taps addressed as one base + immediate offsets.
// ---------------------------------------------------------------------------
__global__ __launch_bounds__(256) void mvf_warp_kernel(
    const float* __restrict__ mvf,     // [PHN][3][DD][HM][WM]
    float* __restrict__ out)           // [5][DD][HH][WW][2]
{
    const int x = threadIdx.x;      // 0..255
    const int y = blockIdx.x;       // 0..255
    const int z = blockIdx.y;       // 0..47
    const int p = blockIdx.z;       // 0..3

    // ---- MVF upsample source coords (linear 128->256, clamp) ----
    // Clamp the base index to WM-2/HM-2 so +1 is always valid; wx/wy may be 1.0,
    // which reproduces the clamped endpoint exactly under linear interpolation.
    float fy = fminf(fmaxf(y * 0.5f - 0.25f, 0.0f), (float)(HM - 1));
    float fx = fminf(fmaxf(x * 0.5f - 0.25f, 0.0f), (float)(WM - 1));
    int   y0 = min((int)fy, HM - 2);
    int   x0 = min((int)fx, WM - 2);
    float wy = fy - (float)y0;
    float wx = fx - (float)x0;

    const int cstr = DD * HM * WM;
    // single base pointer; all 12 taps are immediate offsets off it
    const float* mp = mvf + (((p * 3) * DD + z) * HM + y0) * WM + x0;

    float m[3];
    #pragma unroll
    for (int c = 0; c < 3; ++c) {
        const float* q = mp + c * cstr;
        float v00 = __ldg(q);
        float v01 = __ldg(q + 1);
        float v10 = __ldg(q + WM);
        float v11 = __ldg(q + WM + 1);
        float r0 = v00 + wx * (v01 - v00);
        float r1 = v10 + wx * (v11 - v10);
        m[c] = r0 + wy * (r1 - r0);
    }

    // ---- absolute sample coordinates, flow scaled by (1,2,2) ----
    float cz = (float)z + m[0];
    float cy = (float)y + 2.0f * m[1];
    float cx = (float)x + 2.0f * m[2];

    float zf = floorf(cz), yf = floorf(cy), xf = floorf(cx);
    int   zi = (int)zf,    yi = (int)yf,    xi = (int)xf;
    float wz  = cz - zf;
    float wyy = cy - yf;
    float wxx = cx - xf;

    // ---- x corners: base column xb; corners resolved by 2 SELs ----
    int  xb = min(max(xi, 0), WW - 2);
    bool sel0 = (xi > xb);              // corner0 value lives at xb+1
    bool sel1 = (xi >= xb);             // corner1 at xb+1 unless xi<xb (xi<0)
    float wx0 = ((unsigned)xi       < (unsigned)WW) ? (1.0f - wxx) : 0.0f;
    float wx1 = ((unsigned)(xi + 1) < (unsigned)WW) ? wxx          : 0.0f;

    // ---- z/y rows: clamped indices, zeroed weights, delta addressing ----
    int  zc0 = min(max(zi,     0), DD - 1);
    int  zc1 = min(max(zi + 1, 0), DD - 1);
    int  yc0 = min(max(yi,     0), HH - 1);
    int  yc1 = min(max(yi + 1, 0), HH - 1);
    bool zok0 = ((unsigned)zi       < (unsigned)DD);
    bool zok1 = ((unsigned)(zi + 1) < (unsigned)DD);
    bool yok0 = ((unsigned)yi       < (unsigned)HH);
    bool yok1 = ((unsigned)(yi + 1) < (unsigned)HH);

    float wz0 = 1.0f - wz, wy0 = 1.0f - wyy;
    float wr00 = (zok0 && yok0) ? (wz0 * wy0) : 0.0f;
    float wr01 = (zok0 && yok1) ? (wz0 * wyy) : 0.0f;
    float wr10 = (zok1 && yok0) ? (wz  * wy0) : 0.0f;
    float wr11 = (zok1 && yok1) ? (wz  * wyy) : 0.0f;

    const char* base = (const char*)g_img_h2;
    const char* a00 = base + (((long)((zc0 * HH + yc0) * WW + xb)) << 2);
    long dyo = (long)(yc1 - yc0) << 10;              // *WW*4
    long dzo = (long)(zc1 - zc0) * ((long)HH << 10); // *HH*WW*4
    const char* a01 = a00 + dyo;
    const char* a10 = a00 + dzo;
    const char* a11 = a10 + dyo;

    float acc0 = 0.0f, acc1 = 0.0f;
    {
        const char* addrs[4] = {a00, a01, a10, a11};
        float wrs[4] = {wr00, wr01, wr10, wr11};
        #pragma unroll
        for (int r = 0; r < 4; ++r) {
            unsigned int u0 = __ldg((const unsigned int*)addrs[r]);
            unsigned int u1 = __ldg((const unsigned int*)(addrs[r] + 4));
            float2 p0 = h2_as_f2(sel0 ? u1 : u0);
            float2 p1 = h2_as_f2(sel1 ? u1 : u0);
            float w0 = wrs[r] * wx0;
            float w1 = wrs[r] * wx1;
            acc0 = fmaf(w0, p0.x, fmaf(w1, p1.x, acc0));
            acc1 = fmaf(w0, p0.y, fmaf(w1, p1.y, acc1));
        }
    }

    float2* o = (float2*)out + (((1 + p) * DD + z) * HH + y) * WW + x;
    *o = make_float2(acc0, acc1);
}

extern "C" void kernel_launch(void* const* d_in, const int* in_sizes, int n_in,
                              void* d_out, int out_size)
{
    const float* image = (const float*)d_in[0];   // 6291456 floats
    const float* mvf   = (const float*)d_in[1];   // 9437184 floats
    float* out = (float*)d_out;                   // 31457280 floats

    // pre-pass: channel-0 copy + fp16 pack (4 px per thread)
    const int ng = (DD * HH * WW) / 4;            // 786432 groups of 4 px
    convert_kernel<<<(ng + 255) / 256, 256>>>((const float4*)image, (float4*)out, ng);

    // channels 1..4: fused upsample + warp
    dim3 grid(HH, DD, PHN);
    mvf_warp_kernel<<<grid, 256>>>(mvf, out);
}